// round 5
// baseline (speedup 1.0000x reference)
#include <cuda_runtime.h>

#define D 128
#define Hh 256
#define T_TBL 384
#define DMAXF 12.0f
#define MAXE 524288
#define MAXN 16384

typedef unsigned long long ull;

// ---------------- scratch (no allocs allowed; 16B-aligned: vector LDG/STG used) ----
__device__ __align__(16) float g_filt[T_TBL * D];      // filter table (fp32)
__device__ __align__(16) int   g_cnt[MAXN];
__device__ __align__(16) int   g_off[MAXN + 4];
__device__ __align__(16) int   g_cur[MAXN];
__device__ __align__(16) int   g_ecol[MAXE];
__device__ __align__(16) float g_et[MAXE];             // table coord, or -dist if out of range
__device__ __align__(16) float g_agg[MAXN * D];

// ---------------- helpers ----------------
__device__ __forceinline__ ull pack2(float x, float y) {
    ull r; asm("mov.b64 %0, {%1,%2};" : "=l"(r) : "f"(x), "f"(y)); return r;
}
__device__ __forceinline__ void unpack2(ull v, float& x, float& y) {
    asm("mov.b64 {%0,%1}, %2;" : "=f"(x), "=f"(y) : "l"(v));
}
__device__ __forceinline__ void ffma2(ull& c, ull a, ull b) {
    asm("fma.rn.f32x2 %0, %1, %2, %0;" : "+l"(c) : "l"(a), "l"(b));
}
__device__ __forceinline__ float silu_f(float z) {
    return z / (1.f + __expf(-z));
}

// ---------------- K1: build filter table ----------------
// filt(dist) = silu(dist*W1+b1) @ W2 + b2, tabulated at T_TBL knots over [0, DMAXF]
__global__ void k_table(const float* __restrict__ W1, const float* __restrict__ b1,
                        const float* __restrict__ W2, const float* __restrict__ b2) {
    __shared__ float hid[Hh];
    const int t = blockIdx.x, tid = threadIdx.x;   // 128 threads
    const float dist = t * (DMAXF / (float)(T_TBL - 1));
    for (int j = tid; j < Hh; j += 128) hid[j] = silu_f(dist * W1[j] + b1[j]);
    __syncthreads();
    float s = b2[tid];
#pragma unroll 8
    for (int j = 0; j < Hh; ++j) s += hid[j] * W2[j * D + tid];
    g_filt[t * D + tid] = s;
}

// ---------------- K2: zero counts ----------------
__global__ void k_init(int nn) {
    int i = blockIdx.x * blockDim.x + threadIdx.x;
    if (i < nn) g_cnt[i] = 0;
}

// ---------------- K3: count edges per destination row (edge_indices is int32!) ----
__global__ void k_count(const int* __restrict__ ei, int E, int nn) {
    int e = blockIdx.x * blockDim.x + threadIdx.x;
    if (e < E) {
        unsigned r = (unsigned)ei[e];
        if (r >= (unsigned)nn) r = 0;   // defensive: never trap, fail validation instead
        atomicAdd(&g_cnt[r], 1);
    }
}

// ---------------- K4: exclusive scan (nn <= 16384, one block of 1024) ----------------
__global__ void k_scan(int nn, int Etot) {
    __shared__ int wsum[32];
    const int tid = threadIdx.x;
    const int lane = tid & 31, wid = tid >> 5;
    int vals[16];
    int s = 0;
    const int b0 = tid * 16;
#pragma unroll
    for (int j = 0; j < 16; ++j) {
        int c = (b0 + j < nn) ? g_cnt[b0 + j] : 0;
        vals[j] = s; s += c;
    }
    int inc = s;
#pragma unroll
    for (int d = 1; d < 32; d <<= 1) {
        int o = __shfl_up_sync(0xffffffffu, inc, d);
        if (lane >= d) inc += o;
    }
    if (lane == 31) wsum[wid] = inc;
    __syncthreads();
    if (wid == 0) {
        int v = wsum[lane];
#pragma unroll
        for (int d = 1; d < 32; d <<= 1) {
            int o = __shfl_up_sync(0xffffffffu, v, d);
            if (lane >= d) v += o;
        }
        wsum[lane] = v;
    }
    __syncthreads();
    const int base = (inc - s) + (wid ? wsum[wid - 1] : 0);
#pragma unroll
    for (int j = 0; j < 16; ++j) {
        int i = b0 + j;
        if (i < nn) { int o = base + vals[j]; g_off[i] = o; g_cur[i] = o; }
    }
    if (tid == 0) g_off[nn] = Etot;
}

// ---------------- K5: bucket-scatter edges, compute dist + table coord ----------------
__global__ void k_scatter(const int* __restrict__ ei, const float* __restrict__ x,
                          int E, int nn) {
    int e = blockIdx.x * blockDim.x + threadIdx.x;
    if (e >= E) return;
    unsigned r = (unsigned)ei[e];
    unsigned c = (unsigned)ei[E + e];
    if (r >= (unsigned)nn) r = 0;
    if (c >= (unsigned)nn) c = 0;
    float dx = x[r * 3 + 0] - x[c * 3 + 0];
    float dy = x[r * 3 + 1] - x[c * 3 + 1];
    float dz = x[r * 3 + 2] - x[c * 3 + 2];
    float dist = sqrtf(dx * dx + dy * dy + dz * dz);
    int pos = atomicAdd(&g_cur[r], 1);
    if (pos < E) {
        g_ecol[pos] = (int)c;
        g_et[pos] = (dist <= DMAXF) ? dist * ((float)(T_TBL - 1) / DMAXF) : -dist;
    }
}

// ---------------- K6: aggregate (warp per node; fp32 table in SMEM) ----------------
__global__ __launch_bounds__(512, 1)
void k_agg(const float* __restrict__ h,
           const float* __restrict__ W1, const float* __restrict__ b1,
           const float* __restrict__ W2, const float* __restrict__ b2, int nn) {
    extern __shared__ float tbl[];   // [T_TBL][D]
    for (int i = threadIdx.x; i < T_TBL * D / 4; i += blockDim.x)
        ((float4*)tbl)[i] = ((const float4*)g_filt)[i];
    __syncthreads();

    const int lane = threadIdx.x & 31;
    const int gw = (blockIdx.x * blockDim.x + threadIdx.x) >> 5;
    const int nwarps = (gridDim.x * blockDim.x) >> 5;
    const int d0 = lane * 4;

    for (int v = gw; v < nn; v += nwarps) {
        const int beg = g_off[v], end = g_off[v + 1];
        float ax = 0.f, ay = 0.f, az = 0.f, aw = 0.f;
        for (int e = beg; e < end; ++e) {
            const int c = g_ecol[e];
            const float t = g_et[e];
            const float4 h4 = *(const float4*)(h + c * D + d0);
            float fx, fy, fz, fw;
            if (t >= 0.f) {
                int i0 = (int)t; i0 = min(i0, T_TBL - 2);
                const float fr = t - (float)i0;
                const float4 fa = *(const float4*)(tbl + i0 * D + d0);
                const float4 fb = *(const float4*)(tbl + (i0 + 1) * D + d0);
                fx = fa.x + fr * (fb.x - fa.x);
                fy = fa.y + fr * (fb.y - fa.y);
                fz = fa.z + fr * (fb.z - fa.z);
                fw = fa.w + fr * (fb.w - fa.w);
            } else {
                // exact fallback (dist > DMAXF) — effectively never taken, keeps correctness
                const float dist = -t;
                fx = b2[d0]; fy = b2[d0 + 1]; fz = b2[d0 + 2]; fw = b2[d0 + 3];
                for (int j = 0; j < Hh; ++j) {
                    float hv = silu_f(dist * W1[j] + b1[j]);
                    fx += hv * W2[j * D + d0];
                    fy += hv * W2[j * D + d0 + 1];
                    fz += hv * W2[j * D + d0 + 2];
                    fw += hv * W2[j * D + d0 + 3];
                }
            }
            ax += h4.x * fx; ay += h4.y * fy; az += h4.z * fz; aw += h4.w * fw;
        }
        const float inv = 1.f / fmaxf((float)(end - beg), 1.f);
        float4 o; o.x = ax * inv; o.y = ay * inv; o.z = az * inv; o.w = aw * inv;
        *(float4*)(g_agg + v * D + d0) = o;
    }
}

// ---------------- K7: fused node MLP: [h|agg]@W3 + b3 -> LN -> SiLU -> @W4 + b4 ----
// block = 32 nodes, 256 threads. thread(tx,ty): nodes ty*4+j, GEMM1 cols tx*8..+7 (4 f32x2 pairs)
#define SM_IN_STRIDE 260
__global__ __launch_bounds__(256, 2)
void k_mlp(const float* __restrict__ h,
           const float* __restrict__ W3, const float* __restrict__ b3,
           const float* __restrict__ gam, const float* __restrict__ bet,
           const float* __restrict__ W4, const float* __restrict__ b4,
           float* __restrict__ out, int nn) {
    extern __shared__ float sm[];
    float* in_s = sm;                    // [32][260]
    float* wt = sm + 32 * SM_IN_STRIDE;  // [2][4096] W3 tiles (reused [2][2048] for W4)

    const int tid = threadIdx.x;
    const int tx = tid & 31, ty = tid >> 5;
    const int node0 = blockIdx.x * 32;

    // load input tile [h | agg] -> in_s[node][k]
    {
        const int n = tid >> 3, seg = tid & 7;
        const int gn = min(node0 + n, nn - 1);
        const float* src = (seg < 4) ? (h + gn * D + seg * 32)
                                     : (g_agg + gn * D + (seg - 4) * 32);
        float* dst = in_s + n * SM_IN_STRIDE + seg * 32;
#pragma unroll
        for (int i = 0; i < 8; ++i) ((float4*)dst)[i] = ((const float4*)src)[i];
    }

    // preload W3 tile 0
    float4 pre[4];
#pragma unroll
    for (int i = 0; i < 4; ++i) pre[i] = ((const float4*)W3)[tid + i * 256];
#pragma unroll
    for (int i = 0; i < 4; ++i) ((float4*)wt)[tid + i * 256] = pre[i];
    __syncthreads();

    ull acc[4][4];
#pragma unroll
    for (int j = 0; j < 4; ++j)
#pragma unroll
        for (int p = 0; p < 4; ++p) acc[j][p] = 0ull;

    const float* r0 = in_s + (ty * 4 + 0) * SM_IN_STRIDE;
    const float* r1 = in_s + (ty * 4 + 1) * SM_IN_STRIDE;
    const float* r2 = in_s + (ty * 4 + 2) * SM_IN_STRIDE;
    const float* r3 = in_s + (ty * 4 + 3) * SM_IN_STRIDE;

#pragma unroll 1
    for (int t = 0; t < 16; ++t) {
        float* cur = wt + (t & 1) * 4096;
        float* nxt = wt + ((t + 1) & 1) * 4096;
        if (t < 15) {
            const float4* gs = (const float4*)(W3 + (t + 1) * 4096);
#pragma unroll
            for (int i = 0; i < 4; ++i) pre[i] = gs[tid + i * 256];
        }
#pragma unroll
        for (int kk = 0; kk < 16; ++kk) {
            const int k = t * 16 + kk;
            const ull a0 = pack2(r0[k], r0[k]);
            const ull a1 = pack2(r1[k], r1[k]);
            const ull a2 = pack2(r2[k], r2[k]);
            const ull a3 = pack2(r3[k], r3[k]);
            const ull* br = (const ull*)(cur + kk * 256 + tx * 8);
            const ull b0 = br[0], b1v = br[1], b2v = br[2], b3v = br[3];
            ffma2(acc[0][0], a0, b0); ffma2(acc[0][1], a0, b1v); ffma2(acc[0][2], a0, b2v); ffma2(acc[0][3], a0, b3v);
            ffma2(acc[1][0], a1, b0); ffma2(acc[1][1], a1, b1v); ffma2(acc[1][2], a1, b2v); ffma2(acc[1][3], a1, b3v);
            ffma2(acc[2][0], a2, b0); ffma2(acc[2][1], a2, b1v); ffma2(acc[2][2], a2, b2v); ffma2(acc[2][3], a2, b3v);
            ffma2(acc[3][0], a3, b0); ffma2(acc[3][1], a3, b1v); ffma2(acc[3][2], a3, b2v); ffma2(acc[3][3], a3, b3v);
        }
        if (t < 15) {
#pragma unroll
            for (int i = 0; i < 4; ++i) ((float4*)nxt)[tid + i * 256] = pre[i];
            __syncthreads();
        }
    }

    // bias + LayerNorm + SiLU, write back into in_s (rows are warp-private)
    float2 u[4][4];
    {
        const float4 bbl = *(const float4*)(b3 + tx * 8);
        const float4 bbh = *(const float4*)(b3 + tx * 8 + 4);
        const float bv[8] = {bbl.x, bbl.y, bbl.z, bbl.w, bbh.x, bbh.y, bbh.z, bbh.w};
#pragma unroll
        for (int j = 0; j < 4; ++j)
#pragma unroll
            for (int p = 0; p < 4; ++p) {
                unpack2(acc[j][p], u[j][p].x, u[j][p].y);
                u[j][p].x += bv[2 * p]; u[j][p].y += bv[2 * p + 1];
            }
    }
    {
        const float4 g0 = *(const float4*)(gam + tx * 8);
        const float4 g1 = *(const float4*)(gam + tx * 8 + 4);
        const float4 e0 = *(const float4*)(bet + tx * 8);
        const float4 e1 = *(const float4*)(bet + tx * 8 + 4);
        const float gv[8] = {g0.x, g0.y, g0.z, g0.w, g1.x, g1.y, g1.z, g1.w};
        const float ev[8] = {e0.x, e0.y, e0.z, e0.w, e1.x, e1.y, e1.z, e1.w};
#pragma unroll
        for (int j = 0; j < 4; ++j) {
            float s = 0.f, q = 0.f;
#pragma unroll
            for (int p = 0; p < 4; ++p) {
                s += u[j][p].x + u[j][p].y;
                q += u[j][p].x * u[j][p].x + u[j][p].y * u[j][p].y;
            }
#pragma unroll
            for (int dsh = 16; dsh; dsh >>= 1) {
                s += __shfl_xor_sync(0xffffffffu, s, dsh);
                q += __shfl_xor_sync(0xffffffffu, q, dsh);
            }
            const float mu = s * (1.f / 256.f);
            const float var = q * (1.f / 256.f) - mu * mu;
            const float rs = rsqrtf(var + 1e-5f);
            float* urow = in_s + (ty * 4 + j) * SM_IN_STRIDE + tx * 8;
#pragma unroll
            for (int p = 0; p < 4; ++p) {
                const float ux = (u[j][p].x - mu) * rs * gv[2 * p] + ev[2 * p];
                const float uy = (u[j][p].y - mu) * rs * gv[2 * p + 1] + ev[2 * p + 1];
                urow[2 * p] = silu_f(ux);
                urow[2 * p + 1] = silu_f(uy);
            }
        }
    }
    __syncwarp();

    // GEMM2: out = U @ W4 + b4. thread: 4 nodes x 4 cols (2 f32x2 pairs)
    float4 pre2[2];
#pragma unroll
    for (int i = 0; i < 2; ++i) pre2[i] = ((const float4*)W4)[tid + i * 256];
#pragma unroll
    for (int i = 0; i < 2; ++i) ((float4*)wt)[tid + i * 256] = pre2[i];
    __syncthreads();   // also fences stragglers off W3 tile15 / their in_s rows

    ull acc2[4][2];
#pragma unroll
    for (int j = 0; j < 4; ++j) { acc2[j][0] = 0ull; acc2[j][1] = 0ull; }

#pragma unroll 1
    for (int t = 0; t < 16; ++t) {
        float* cur = wt + (t & 1) * 2048;
        float* nxt = wt + ((t + 1) & 1) * 2048;
        if (t < 15) {
            const float4* gs = (const float4*)(W4 + (t + 1) * 2048);
            pre2[0] = gs[tid]; pre2[1] = gs[tid + 256];
        }
#pragma unroll
        for (int kk = 0; kk < 16; ++kk) {
            const int k = t * 16 + kk;
            const ull a0 = pack2(r0[k], r0[k]);
            const ull a1 = pack2(r1[k], r1[k]);
            const ull a2 = pack2(r2[k], r2[k]);
            const ull a3 = pack2(r3[k], r3[k]);
            const ull* br = (const ull*)(cur + kk * 128 + tx * 4);
            const ull b0 = br[0], b1v = br[1];
            ffma2(acc2[0][0], a0, b0); ffma2(acc2[0][1], a0, b1v);
            ffma2(acc2[1][0], a1, b0); ffma2(acc2[1][1], a1, b1v);
            ffma2(acc2[2][0], a2, b0); ffma2(acc2[2][1], a2, b1v);
            ffma2(acc2[3][0], a3, b0); ffma2(acc2[3][1], a3, b1v);
        }
        if (t < 15) {
            ((float4*)nxt)[tid] = pre2[0];
            ((float4*)nxt)[tid + 256] = pre2[1];
            __syncthreads();
        }
    }

    // epilogue
    const float4 b4v = *(const float4*)(b4 + tx * 4);
#pragma unroll
    for (int j = 0; j < 4; ++j) {
        float2 o0, o1;
        unpack2(acc2[j][0], o0.x, o0.y);
        unpack2(acc2[j][1], o1.x, o1.y);
        o0.x += b4v.x; o0.y += b4v.y; o1.x += b4v.z; o1.y += b4v.w;
        const int gn = node0 + ty * 4 + j;
        if (gn < nn) {
            float2* op = (float2*)(out + gn * D + tx * 4);
            op[0] = o0; op[1] = o1;
        }
    }
}

// ---------------- host ----------------
extern "C" void kernel_launch(void* const* d_in, const int* in_sizes, int n_in,
                              void* d_out, int out_size) {
    const float* x = (const float*)d_in[0];
    const float* h = (const float*)d_in[1];
    const int* ei = (const int*)d_in[2];    // edge_indices: int32 (JAX default, no x64)
    int base = 3;
    if (n_in >= 14 && in_sizes[3] == 1) base = 4;   // batch_size scalar present
    const float* W1 = (const float*)d_in[base + 0];
    const float* b1 = (const float*)d_in[base + 1];
    const float* W2 = (const float*)d_in[base + 2];
    const float* b2 = (const float*)d_in[base + 3];
    const float* W3 = (const float*)d_in[base + 4];
    const float* b3 = (const float*)d_in[base + 5];
    const float* gam = (const float*)d_in[base + 6];
    const float* bet = (const float*)d_in[base + 7];
    const float* W4 = (const float*)d_in[base + 8];
    const float* b4 = (const float*)d_in[base + 9];
    float* out = (float*)d_out;

    int E = in_sizes[2] / 2;
    int nn = in_sizes[1] / D;
    if (E > MAXE) E = MAXE;
    if (nn > MAXN) nn = MAXN;

    const int agg_smem = T_TBL * D * 4;                          // 196608
    const int mlp_smem = (32 * SM_IN_STRIDE + 2 * 4096) * 4;     // 66048
    cudaFuncSetAttribute(k_agg, cudaFuncAttributeMaxDynamicSharedMemorySize, agg_smem);
    cudaFuncSetAttribute(k_mlp, cudaFuncAttributeMaxDynamicSharedMemorySize, mlp_smem);

    k_table<<<T_TBL, 128>>>(W1, b1, W2, b2);
    k_init<<<(nn + 255) / 256, 256>>>(nn);
    k_count<<<(E + 255) / 256, 256>>>(ei, E, nn);
    k_scan<<<1, 1024>>>(nn, E);
    k_scatter<<<(E + 255) / 256, 256>>>(ei, x, E, nn);
    k_agg<<<148, 512, agg_smem>>>(h, W1, b1, W2, b2, nn);
    k_mlp<<<(nn + 31) / 32, 256, mlp_smem>>>(h, W3, b3, gam, bet, W4, b4, out, nn);
}

// round 6
// speedup vs baseline: 1.1716x; 1.1716x over previous
#include <cuda_runtime.h>

#define D 128
#define Hh 256
#define T_TBL 384
#define DMAXF 12.0f
#define MAXE 524288
#define MAXN 16384

typedef unsigned long long ull;

// ---------------- scratch (no allocs allowed; 16B-aligned: vector LDG/STG used) ----
__device__ __align__(16) float g_filt[T_TBL * D];      // filter table (fp32)
__device__ __align__(16) int   g_cnt[MAXN];
__device__ __align__(16) int   g_off[MAXN + 4];
__device__ __align__(16) int   g_cur[MAXN];
__device__ __align__(16) int   g_ecol[MAXE];
__device__ __align__(16) float g_et[MAXE];             // table coord, or -dist if out of range
__device__ __align__(16) float g_agg[MAXN * D];

// ---------------- helpers ----------------
__device__ __forceinline__ ull pack2(float x, float y) {
    ull r; asm("mov.b64 %0, {%1,%2};" : "=l"(r) : "f"(x), "f"(y)); return r;
}
__device__ __forceinline__ void unpack2(ull v, float& x, float& y) {
    asm("mov.b64 {%0,%1}, %2;" : "=f"(x), "=f"(y) : "l"(v));
}
__device__ __forceinline__ void ffma2(ull& c, ull a, ull b) {
    asm("fma.rn.f32x2 %0, %1, %2, %0;" : "+l"(c) : "l"(a), "l"(b));
}
__device__ __forceinline__ float silu_f(float z) {
    return z / (1.f + __expf(-z));
}

// ---------------- K1: build filter table (+ zero g_cnt; 384*128 threads >= MAXN) ----
__global__ void k_table(const float* __restrict__ W1, const float* __restrict__ b1,
                        const float* __restrict__ W2, const float* __restrict__ b2) {
    __shared__ float hid[Hh];
    const int t = blockIdx.x, tid = threadIdx.x;   // 128 threads
    const int gid = t * 128 + tid;
    if (gid < MAXN) g_cnt[gid] = 0;
    const float dist = t * (DMAXF / (float)(T_TBL - 1));
    for (int j = tid; j < Hh; j += 128) hid[j] = silu_f(dist * W1[j] + b1[j]);
    __syncthreads();
    float s = b2[tid];
#pragma unroll 8
    for (int j = 0; j < Hh; ++j) s += hid[j] * W2[j * D + tid];
    g_filt[t * D + tid] = s;
}

// ---------------- K2: count edges per destination row (4 edges/thread) ----------------
__global__ void k_count(const int* __restrict__ ei, int E, int nn) {
    int e = (blockIdx.x * blockDim.x + threadIdx.x) * 4;
    if (e + 3 < E) {
        int4 v = *(const int4*)(ei + e);
        unsigned r0 = (unsigned)v.x, r1 = (unsigned)v.y, r2 = (unsigned)v.z, r3 = (unsigned)v.w;
        if (r0 >= (unsigned)nn) r0 = 0;
        if (r1 >= (unsigned)nn) r1 = 0;
        if (r2 >= (unsigned)nn) r2 = 0;
        if (r3 >= (unsigned)nn) r3 = 0;
        atomicAdd(&g_cnt[r0], 1); atomicAdd(&g_cnt[r1], 1);
        atomicAdd(&g_cnt[r2], 1); atomicAdd(&g_cnt[r3], 1);
    } else {
        for (; e < E; ++e) {
            unsigned r = (unsigned)ei[e];
            if (r >= (unsigned)nn) r = 0;
            atomicAdd(&g_cnt[r], 1);
        }
    }
}

// ---------------- K3: exclusive scan of fixed MAXN counts (int4 vectorized) ----------
// counts beyond nn are zero, so g_off degenerates to E there (harmless).
__global__ void k_scan(int Etot) {
    __shared__ int wsum[32];
    const int tid = threadIdx.x;
    const int lane = tid & 31, wid = tid >> 5;
    const int b0 = tid * 16;
    int4 cv[4];
    const int4* cp = (const int4*)(g_cnt + b0);
#pragma unroll
    for (int q = 0; q < 4; ++q) cv[q] = cp[q];
    int vals[16];
    int s = 0;
#pragma unroll
    for (int q = 0; q < 4; ++q) {
        vals[q * 4 + 0] = s; s += cv[q].x;
        vals[q * 4 + 1] = s; s += cv[q].y;
        vals[q * 4 + 2] = s; s += cv[q].z;
        vals[q * 4 + 3] = s; s += cv[q].w;
    }
    int inc = s;
#pragma unroll
    for (int d = 1; d < 32; d <<= 1) {
        int o = __shfl_up_sync(0xffffffffu, inc, d);
        if (lane >= d) inc += o;
    }
    if (lane == 31) wsum[wid] = inc;
    __syncthreads();
    if (wid == 0) {
        int v = wsum[lane];
#pragma unroll
        for (int d = 1; d < 32; d <<= 1) {
            int o = __shfl_up_sync(0xffffffffu, v, d);
            if (lane >= d) v += o;
        }
        wsum[lane] = v;
    }
    __syncthreads();
    const int base = (inc - s) + (wid ? wsum[wid - 1] : 0);
    int4* op = (int4*)(g_off + b0);
    int4* up = (int4*)(g_cur + b0);
#pragma unroll
    for (int q = 0; q < 4; ++q) {
        int4 o;
        o.x = base + vals[q * 4 + 0];
        o.y = base + vals[q * 4 + 1];
        o.z = base + vals[q * 4 + 2];
        o.w = base + vals[q * 4 + 3];
        op[q] = o; up[q] = o;
    }
    if (tid == 1023) g_off[MAXN] = Etot;
}

// ---------------- K4: bucket-scatter edges (4 edges/thread) ----------------
__global__ void k_scatter(const int* __restrict__ ei, const float* __restrict__ x,
                          int E, int nn) {
    const int e0 = (blockIdx.x * blockDim.x + threadIdx.x) * 4;
#pragma unroll
    for (int j = 0; j < 4; ++j) {
        const int e = e0 + j;
        if (e >= E) return;
        unsigned r = (unsigned)ei[e];
        unsigned c = (unsigned)ei[E + e];
        if (r >= (unsigned)nn) r = 0;
        if (c >= (unsigned)nn) c = 0;
        float dx = x[r * 3 + 0] - x[c * 3 + 0];
        float dy = x[r * 3 + 1] - x[c * 3 + 1];
        float dz = x[r * 3 + 2] - x[c * 3 + 2];
        float dist = sqrtf(dx * dx + dy * dy + dz * dz);
        int pos = atomicAdd(&g_cur[r], 1);
        if (pos < E) {
            g_ecol[pos] = (int)c;
            g_et[pos] = (dist <= DMAXF) ? dist * ((float)(T_TBL - 1) / DMAXF) : -dist;
        }
    }
}

// ---------------- K5: aggregate (warp per node; fp32 table in SMEM; MLP=8) ---------
__global__ __launch_bounds__(512, 1)
void k_agg(const float* __restrict__ h,
           const float* __restrict__ W1, const float* __restrict__ b1,
           const float* __restrict__ W2, const float* __restrict__ b2, int nn) {
    extern __shared__ float tbl[];   // [T_TBL][D]
    for (int i = threadIdx.x; i < T_TBL * D / 4; i += blockDim.x)
        ((float4*)tbl)[i] = ((const float4*)g_filt)[i];
    __syncthreads();

    const int lane = threadIdx.x & 31;
    const int gw = (blockIdx.x * blockDim.x + threadIdx.x) >> 5;
    const int nwarps = (gridDim.x * blockDim.x) >> 5;
    const int d0 = lane * 4;

    for (int v = gw; v < nn; v += nwarps) {
        const int beg = g_off[v], end = g_off[v + 1];
        float ax = 0.f, ay = 0.f, az = 0.f, aw = 0.f;

        int e0 = beg;
        // main loop: 8 edges per round, all 8 h-gathers issued before consumption
        for (; e0 + 8 <= end; e0 += 8) {
            int cc = 0; float tv = 0.f;
            if (lane < 8) { cc = g_ecol[e0 + lane]; tv = g_et[e0 + lane]; }
            float4 hb[8];
            float  tc[8];
#pragma unroll
            for (int j = 0; j < 8; ++j) {
                const int c = __shfl_sync(0xffffffffu, cc, j);
                tc[j] = __shfl_sync(0xffffffffu, tv, j);
                hb[j] = *(const float4*)(h + c * D + d0);
            }
#pragma unroll
            for (int j = 0; j < 8; ++j) {
                const float t = tc[j];
                float fx, fy, fz, fw;
                if (t >= 0.f) {
                    int i0 = (int)t; i0 = min(i0, T_TBL - 2);
                    const float fr = t - (float)i0;
                    const float4 fa = *(const float4*)(tbl + i0 * D + d0);
                    const float4 fb = *(const float4*)(tbl + (i0 + 1) * D + d0);
                    fx = fa.x + fr * (fb.x - fa.x);
                    fy = fa.y + fr * (fb.y - fa.y);
                    fz = fa.z + fr * (fb.z - fa.z);
                    fw = fa.w + fr * (fb.w - fa.w);
                } else {
                    const float dist = -t;   // exact fallback (dist > DMAXF), ~never taken
                    fx = b2[d0]; fy = b2[d0 + 1]; fz = b2[d0 + 2]; fw = b2[d0 + 3];
                    for (int q = 0; q < Hh; ++q) {
                        float hv = silu_f(dist * W1[q] + b1[q]);
                        fx += hv * W2[q * D + d0];
                        fy += hv * W2[q * D + d0 + 1];
                        fz += hv * W2[q * D + d0 + 2];
                        fw += hv * W2[q * D + d0 + 3];
                    }
                }
                ax += hb[j].x * fx; ay += hb[j].y * fy;
                az += hb[j].z * fz; aw += hb[j].w * fw;
            }
        }
        // tail
        for (; e0 < end; ++e0) {
            const int c = g_ecol[e0];
            const float t = g_et[e0];
            const float4 h4 = *(const float4*)(h + c * D + d0);
            float fx, fy, fz, fw;
            if (t >= 0.f) {
                int i0 = (int)t; i0 = min(i0, T_TBL - 2);
                const float fr = t - (float)i0;
                const float4 fa = *(const float4*)(tbl + i0 * D + d0);
                const float4 fb = *(const float4*)(tbl + (i0 + 1) * D + d0);
                fx = fa.x + fr * (fb.x - fa.x);
                fy = fa.y + fr * (fb.y - fa.y);
                fz = fa.z + fr * (fb.z - fa.z);
                fw = fa.w + fr * (fb.w - fa.w);
            } else {
                const float dist = -t;
                fx = b2[d0]; fy = b2[d0 + 1]; fz = b2[d0 + 2]; fw = b2[d0 + 3];
                for (int q = 0; q < Hh; ++q) {
                    float hv = silu_f(dist * W1[q] + b1[q]);
                    fx += hv * W2[q * D + d0];
                    fy += hv * W2[q * D + d0 + 1];
                    fz += hv * W2[q * D + d0 + 2];
                    fw += hv * W2[q * D + d0 + 3];
                }
            }
            ax += h4.x * fx; ay += h4.y * fy; az += h4.z * fz; aw += h4.w * fw;
        }

        const float inv = 1.f / fmaxf((float)(end - beg), 1.f);
        float4 o; o.x = ax * inv; o.y = ay * inv; o.z = az * inv; o.w = aw * inv;
        *(float4*)(g_agg + v * D + d0) = o;
    }
}

// ---------------- K6: fused node MLP: [h|agg]@W3 + b3 -> LN -> SiLU -> @W4 + b4 ----
// block = 32 nodes, 256 threads. thread(tx,ty): nodes ty*4+j, GEMM1 cols tx*8..+7 (4 f32x2 pairs)
#define SM_IN_STRIDE 260
__global__ __launch_bounds__(256, 2)
void k_mlp(const float* __restrict__ h,
           const float* __restrict__ W3, const float* __restrict__ b3,
           const float* __restrict__ gam, const float* __restrict__ bet,
           const float* __restrict__ W4, const float* __restrict__ b4,
           float* __restrict__ out, int nn) {
    extern __shared__ float sm[];
    float* in_s = sm;                    // [32][260]
    float* wt = sm + 32 * SM_IN_STRIDE;  // [2][4096] W3 tiles (reused [2][2048] for W4)

    const int tid = threadIdx.x;
    const int tx = tid & 31, ty = tid >> 5;
    const int node0 = blockIdx.x * 32;

    // load input tile [h | agg] -> in_s[node][k]
    {
        const int n = tid >> 3, seg = tid & 7;
        const int gn = min(node0 + n, nn - 1);
        const float* src = (seg < 4) ? (h + gn * D + seg * 32)
                                     : (g_agg + gn * D + (seg - 4) * 32);
        float* dst = in_s + n * SM_IN_STRIDE + seg * 32;
#pragma unroll
        for (int i = 0; i < 8; ++i) ((float4*)dst)[i] = ((const float4*)src)[i];
    }

    // preload W3 tile 0
    float4 pre[4];
#pragma unroll
    for (int i = 0; i < 4; ++i) pre[i] = ((const float4*)W3)[tid + i * 256];
#pragma unroll
    for (int i = 0; i < 4; ++i) ((float4*)wt)[tid + i * 256] = pre[i];
    __syncthreads();

    ull acc[4][4];
#pragma unroll
    for (int j = 0; j < 4; ++j)
#pragma unroll
        for (int p = 0; p < 4; ++p) acc[j][p] = 0ull;

    const float* r0 = in_s + (ty * 4 + 0) * SM_IN_STRIDE;
    const float* r1 = in_s + (ty * 4 + 1) * SM_IN_STRIDE;
    const float* r2 = in_s + (ty * 4 + 2) * SM_IN_STRIDE;
    const float* r3 = in_s + (ty * 4 + 3) * SM_IN_STRIDE;

#pragma unroll 1
    for (int t = 0; t < 16; ++t) {
        float* cur = wt + (t & 1) * 4096;
        float* nxt = wt + ((t + 1) & 1) * 4096;
        if (t < 15) {
            const float4* gs = (const float4*)(W3 + (t + 1) * 4096);
#pragma unroll
            for (int i = 0; i < 4; ++i) pre[i] = gs[tid + i * 256];
        }
#pragma unroll
        for (int kk = 0; kk < 16; ++kk) {
            const int k = t * 16 + kk;
            const ull a0 = pack2(r0[k], r0[k]);
            const ull a1 = pack2(r1[k], r1[k]);
            const ull a2 = pack2(r2[k], r2[k]);
            const ull a3 = pack2(r3[k], r3[k]);
            const ull* br = (const ull*)(cur + kk * 256 + tx * 8);
            const ull b0 = br[0], b1v = br[1], b2v = br[2], b3v = br[3];
            ffma2(acc[0][0], a0, b0); ffma2(acc[0][1], a0, b1v); ffma2(acc[0][2], a0, b2v); ffma2(acc[0][3], a0, b3v);
            ffma2(acc[1][0], a1, b0); ffma2(acc[1][1], a1, b1v); ffma2(acc[1][2], a1, b2v); ffma2(acc[1][3], a1, b3v);
            ffma2(acc[2][0], a2, b0); ffma2(acc[2][1], a2, b1v); ffma2(acc[2][2], a2, b2v); ffma2(acc[2][3], a2, b3v);
            ffma2(acc[3][0], a3, b0); ffma2(acc[3][1], a3, b1v); ffma2(acc[3][2], a3, b2v); ffma2(acc[3][3], a3, b3v);
        }
        if (t < 15) {
#pragma unroll
            for (int i = 0; i < 4; ++i) ((float4*)nxt)[tid + i * 256] = pre[i];
            __syncthreads();
        }
    }

    // bias + LayerNorm + SiLU, write back into in_s (rows are warp-private)
    float2 u[4][4];
    {
        const float4 bbl = *(const float4*)(b3 + tx * 8);
        const float4 bbh = *(const float4*)(b3 + tx * 8 + 4);
        const float bv[8] = {bbl.x, bbl.y, bbl.z, bbl.w, bbh.x, bbh.y, bbh.z, bbh.w};
#pragma unroll
        for (int j = 0; j < 4; ++j)
#pragma unroll
            for (int p = 0; p < 4; ++p) {
                unpack2(acc[j][p], u[j][p].x, u[j][p].y);
                u[j][p].x += bv[2 * p]; u[j][p].y += bv[2 * p + 1];
            }
    }
    {
        const float4 g0 = *(const float4*)(gam + tx * 8);
        const float4 g1 = *(const float4*)(gam + tx * 8 + 4);
        const float4 e0 = *(const float4*)(bet + tx * 8);
        const float4 e1 = *(const float4*)(bet + tx * 8 + 4);
        const float gv[8] = {g0.x, g0.y, g0.z, g0.w, g1.x, g1.y, g1.z, g1.w};
        const float ev[8] = {e0.x, e0.y, e0.z, e0.w, e1.x, e1.y, e1.z, e1.w};
#pragma unroll
        for (int j = 0; j < 4; ++j) {
            float s = 0.f, q = 0.f;
#pragma unroll
            for (int p = 0; p < 4; ++p) {
                s += u[j][p].x + u[j][p].y;
                q += u[j][p].x * u[j][p].x + u[j][p].y * u[j][p].y;
            }
#pragma unroll
            for (int dsh = 16; dsh; dsh >>= 1) {
                s += __shfl_xor_sync(0xffffffffu, s, dsh);
                q += __shfl_xor_sync(0xffffffffu, q, dsh);
            }
            const float mu = s * (1.f / 256.f);
            const float var = q * (1.f / 256.f) - mu * mu;
            const float rs = rsqrtf(var + 1e-5f);
            float* urow = in_s + (ty * 4 + j) * SM_IN_STRIDE + tx * 8;
#pragma unroll
            for (int p = 0; p < 4; ++p) {
                const float ux = (u[j][p].x - mu) * rs * gv[2 * p] + ev[2 * p];
                const float uy = (u[j][p].y - mu) * rs * gv[2 * p + 1] + ev[2 * p + 1];
                urow[2 * p] = silu_f(ux);
                urow[2 * p + 1] = silu_f(uy);
            }
        }
    }
    __syncwarp();

    // GEMM2: out = U @ W4 + b4. thread: 4 nodes x 4 cols (2 f32x2 pairs)
    float4 pre2[2];
#pragma unroll
    for (int i = 0; i < 2; ++i) pre2[i] = ((const float4*)W4)[tid + i * 256];
#pragma unroll
    for (int i = 0; i < 2; ++i) ((float4*)wt)[tid + i * 256] = pre2[i];
    __syncthreads();   // also fences stragglers off W3 tile15 / their in_s rows

    ull acc2[4][2];
#pragma unroll
    for (int j = 0; j < 4; ++j) { acc2[j][0] = 0ull; acc2[j][1] = 0ull; }

#pragma unroll 1
    for (int t = 0; t < 16; ++t) {
        float* cur = wt + (t & 1) * 2048;
        float* nxt = wt + ((t + 1) & 1) * 2048;
        if (t < 15) {
            const float4* gs = (const float4*)(W4 + (t + 1) * 2048);
            pre2[0] = gs[tid]; pre2[1] = gs[tid + 256];
        }
#pragma unroll
        for (int kk = 0; kk < 16; ++kk) {
            const int k = t * 16 + kk;
            const ull a0 = pack2(r0[k], r0[k]);
            const ull a1 = pack2(r1[k], r1[k]);
            const ull a2 = pack2(r2[k], r2[k]);
            const ull a3 = pack2(r3[k], r3[k]);
            const ull* br = (const ull*)(cur + kk * 128 + tx * 4);
            const ull b0 = br[0], b1v = br[1];
            ffma2(acc2[0][0], a0, b0); ffma2(acc2[0][1], a0, b1v);
            ffma2(acc2[1][0], a1, b0); ffma2(acc2[1][1], a1, b1v);
            ffma2(acc2[2][0], a2, b0); ffma2(acc2[2][1], a2, b1v);
            ffma2(acc2[3][0], a3, b0); ffma2(acc2[3][1], a3, b1v);
        }
        if (t < 15) {
            ((float4*)nxt)[tid] = pre2[0];
            ((float4*)nxt)[tid + 256] = pre2[1];
            __syncthreads();
        }
    }

    // epilogue
    const float4 b4v = *(const float4*)(b4 + tx * 4);
#pragma unroll
    for (int j = 0; j < 4; ++j) {
        float2 o0, o1;
        unpack2(acc2[j][0], o0.x, o0.y);
        unpack2(acc2[j][1], o1.x, o1.y);
        o0.x += b4v.x; o0.y += b4v.y; o1.x += b4v.z; o1.y += b4v.w;
        const int gn = node0 + ty * 4 + j;
        if (gn < nn) {
            float2* op = (float2*)(out + gn * D + tx * 4);
            op[0] = o0; op[1] = o1;
        }
    }
}

// ---------------- host ----------------
extern "C" void kernel_launch(void* const* d_in, const int* in_sizes, int n_in,
                              void* d_out, int out_size) {
    const float* x = (const float*)d_in[0];
    const float* h = (const float*)d_in[1];
    const int* ei = (const int*)d_in[2];    // edge_indices: int32
    int base = 3;
    if (n_in >= 14 && in_sizes[3] == 1) base = 4;   // batch_size scalar present
    const float* W1 = (const float*)d_in[base + 0];
    const float* b1 = (const float*)d_in[base + 1];
    const float* W2 = (const float*)d_in[base + 2];
    const float* b2 = (const float*)d_in[base + 3];
    const float* W3 = (const float*)d_in[base + 4];
    const float* b3 = (const float*)d_in[base + 5];
    const float* gam = (const float*)d_in[base + 6];
    const float* bet = (const float*)d_in[base + 7];
    const float* W4 = (const float*)d_in[base + 8];
    const float* b4 = (const float*)d_in[base + 9];
    float* out = (float*)d_out;

    int E = in_sizes[2] / 2;
    int nn = in_sizes[1] / D;
    if (E > MAXE) E = MAXE;
    if (nn > MAXN) nn = MAXN;

    const int agg_smem = T_TBL * D * 4;                          // 196608
    const int mlp_smem = (32 * SM_IN_STRIDE + 2 * 4096) * 4;     // 66048
    cudaFuncSetAttribute(k_agg, cudaFuncAttributeMaxDynamicSharedMemorySize, agg_smem);
    cudaFuncSetAttribute(k_mlp, cudaFuncAttributeMaxDynamicSharedMemorySize, mlp_smem);

    const int e4 = (E + 3) / 4;
    k_table<<<T_TBL, 128>>>(W1, b1, W2, b2);
    k_count<<<(e4 + 255) / 256, 256>>>(ei, E, nn);
    k_scan<<<1, 1024>>>(E);
    k_scatter<<<(e4 + 255) / 256, 256>>>(ei, x, E, nn);
    k_agg<<<148, 512, agg_smem>>>(h, W1, b1, W2, b2, nn);
    k_mlp<<<(nn + 31) / 32, 256, mlp_smem>>>(h, W3, b3, gam, bet, W4, b4, out, nn);
}

// round 7
// speedup vs baseline: 1.2354x; 1.0545x over previous
#include <cuda_runtime.h>

#define D 128
#define Hh 256
#define T_TBL 384
#define DMAXF 12.0f
#define MAXE 524288
#define MAXN 16384

typedef unsigned long long ull;

// ---------------- scratch (no allocs allowed; 16B-aligned) ----------------
__device__ __align__(16) float g_filt[T_TBL * D];      // filter table (fp32)
__device__ __align__(16) int   g_cnt[MAXN];
__device__ __align__(16) int   g_off[MAXN + 4];
__device__ __align__(16) int   g_rank[MAXE];           // within-row rank of each edge
__device__ __align__(16) int2  g_edge[MAXE];           // {col, float_bits(tcoord)} bucketed
__device__ __align__(16) float g_agg[MAXN * D];

// ---------------- helpers ----------------
__device__ __forceinline__ ull pack2(float x, float y) {
    ull r; asm("mov.b64 %0, {%1,%2};" : "=l"(r) : "f"(x), "f"(y)); return r;
}
__device__ __forceinline__ void unpack2(ull v, float& x, float& y) {
    asm("mov.b64 {%0,%1}, %2;" : "=f"(x), "=f"(y) : "l"(v));
}
__device__ __forceinline__ void ffma2(ull& c, ull a, ull b) {
    asm("fma.rn.f32x2 %0, %1, %2, %0;" : "+l"(c) : "l"(a), "l"(b));
}
__device__ __forceinline__ float silu_f(float z) {
    return z / (1.f + __expf(-z));
}

// ---------------- K1: build filter table (+ zero g_cnt; 384*128 threads >= MAXN) ----
__global__ void k_table(const float* __restrict__ W1, const float* __restrict__ b1,
                        const float* __restrict__ W2, const float* __restrict__ b2) {
    __shared__ float hid[Hh];
    const int t = blockIdx.x, tid = threadIdx.x;   // 128 threads
    const int gid = t * 128 + tid;
    if (gid < MAXN) g_cnt[gid] = 0;
    const float dist = t * (DMAXF / (float)(T_TBL - 1));
    for (int j = tid; j < Hh; j += 128) hid[j] = silu_f(dist * W1[j] + b1[j]);
    __syncthreads();
    float s = b2[tid];
#pragma unroll 8
    for (int j = 0; j < Hh; ++j) s += hid[j] * W2[j * D + tid];
    g_filt[t * D + tid] = s;
}

// ---------------- K2: count edges per row; record each edge's rank ----------------
__global__ void k_count(const int* __restrict__ ei, int E, int nn) {
    int e = (blockIdx.x * blockDim.x + threadIdx.x) * 4;
    if (e + 3 < E) {
        int4 v = *(const int4*)(ei + e);
        unsigned r0 = (unsigned)v.x, r1 = (unsigned)v.y, r2 = (unsigned)v.z, r3 = (unsigned)v.w;
        if (r0 >= (unsigned)nn) r0 = 0;
        if (r1 >= (unsigned)nn) r1 = 0;
        if (r2 >= (unsigned)nn) r2 = 0;
        if (r3 >= (unsigned)nn) r3 = 0;
        int4 k;
        k.x = atomicAdd(&g_cnt[r0], 1);
        k.y = atomicAdd(&g_cnt[r1], 1);
        k.z = atomicAdd(&g_cnt[r2], 1);
        k.w = atomicAdd(&g_cnt[r3], 1);
        *(int4*)(g_rank + e) = k;
    } else {
        for (; e < E; ++e) {
            unsigned r = (unsigned)ei[e];
            if (r >= (unsigned)nn) r = 0;
            g_rank[e] = atomicAdd(&g_cnt[r], 1);
        }
    }
}

// ---------------- K3: exclusive scan of fixed MAXN counts (int4 vectorized) ----------
__global__ void k_scan(int Etot) {
    __shared__ int wsum[32];
    const int tid = threadIdx.x;
    const int lane = tid & 31, wid = tid >> 5;
    const int b0 = tid * 16;
    int4 cv[4];
    const int4* cp = (const int4*)(g_cnt + b0);
#pragma unroll
    for (int q = 0; q < 4; ++q) cv[q] = cp[q];
    int vals[16];
    int s = 0;
#pragma unroll
    for (int q = 0; q < 4; ++q) {
        vals[q * 4 + 0] = s; s += cv[q].x;
        vals[q * 4 + 1] = s; s += cv[q].y;
        vals[q * 4 + 2] = s; s += cv[q].z;
        vals[q * 4 + 3] = s; s += cv[q].w;
    }
    int inc = s;
#pragma unroll
    for (int d = 1; d < 32; d <<= 1) {
        int o = __shfl_up_sync(0xffffffffu, inc, d);
        if (lane >= d) inc += o;
    }
    if (lane == 31) wsum[wid] = inc;
    __syncthreads();
    if (wid == 0) {
        int v = wsum[lane];
#pragma unroll
        for (int d = 1; d < 32; d <<= 1) {
            int o = __shfl_up_sync(0xffffffffu, v, d);
            if (lane >= d) v += o;
        }
        wsum[lane] = v;
    }
    __syncthreads();
    const int base = (inc - s) + (wid ? wsum[wid - 1] : 0);
    int4* op = (int4*)(g_off + b0);
#pragma unroll
    for (int q = 0; q < 4; ++q) {
        int4 o;
        o.x = base + vals[q * 4 + 0];
        o.y = base + vals[q * 4 + 1];
        o.z = base + vals[q * 4 + 2];
        o.w = base + vals[q * 4 + 3];
        op[q] = o;
    }
    if (tid == 1023) g_off[MAXN] = Etot;
}

// ---------------- K4: atomic-free bucket scatter (pos = off[r] + rank[e]) ----------
__global__ void k_scatter(const int* __restrict__ ei, const float* __restrict__ x,
                          int E, int nn) {
    const int e = blockIdx.x * blockDim.x + threadIdx.x;
    if (e >= E) return;
    unsigned r = (unsigned)__ldg(ei + e);
    unsigned c = (unsigned)__ldg(ei + E + e);
    if (r >= (unsigned)nn) r = 0;
    if (c >= (unsigned)nn) c = 0;
    const int pos = g_off[r] + g_rank[e];
    const float ax = __ldg(x + r * 3 + 0), bx = __ldg(x + c * 3 + 0);
    const float ay = __ldg(x + r * 3 + 1), by = __ldg(x + c * 3 + 1);
    const float az = __ldg(x + r * 3 + 2), bz = __ldg(x + c * 3 + 2);
    const float dx = ax - bx, dy = ay - by, dz = az - bz;
    const float dist = sqrtf(dx * dx + dy * dy + dz * dz);
    const float t = (dist <= DMAXF) ? dist * ((float)(T_TBL - 1) / DMAXF) : -dist;
    int2 o; o.x = (int)c; o.y = __float_as_int(t);
    g_edge[pos] = o;
}

// ---------------- K5: aggregate (warp per node; fp32 table in SMEM; MLP=8) ---------
__global__ __launch_bounds__(512, 1)
void k_agg(const float* __restrict__ h,
           const float* __restrict__ W1, const float* __restrict__ b1,
           const float* __restrict__ W2, const float* __restrict__ b2, int nn) {
    extern __shared__ float tbl[];   // [T_TBL][D]
    for (int i = threadIdx.x; i < T_TBL * D / 4; i += blockDim.x)
        ((float4*)tbl)[i] = ((const float4*)g_filt)[i];
    __syncthreads();

    const int lane = threadIdx.x & 31;
    const int gw = (blockIdx.x * blockDim.x + threadIdx.x) >> 5;
    const int nwarps = (gridDim.x * blockDim.x) >> 5;
    const int d0 = lane * 4;

    for (int v = gw; v < nn; v += nwarps) {
        const int beg = g_off[v], end = g_off[v + 1];
        float ax = 0.f, ay = 0.f, az = 0.f, aw = 0.f;

        // prefetched edge descriptor for the upcoming 8-edge round (lanes 0..7)
        int2 ed = make_int2(0, 0);
        if (lane < 8 && beg + lane < end) ed = g_edge[beg + lane];

        int e0 = beg;
        for (; e0 + 8 <= end; e0 += 8) {
            const int2 cur = ed;
            if (lane < 8 && e0 + 8 + lane < end) ed = g_edge[e0 + 8 + lane];

            float4 hb[8];
            float  tc[8];
#pragma unroll
            for (int j = 0; j < 8; ++j) {
                const int c = __shfl_sync(0xffffffffu, cur.x, j);
                tc[j] = __int_as_float(__shfl_sync(0xffffffffu, cur.y, j));
                hb[j] = *(const float4*)(h + c * D + d0);
            }
#pragma unroll
            for (int j = 0; j < 8; ++j) {
                const float t = tc[j];
                float fx, fy, fz, fw;
                if (t >= 0.f) {
                    int i0 = (int)t; i0 = min(i0, T_TBL - 2);
                    const float fr = t - (float)i0;
                    const float4 fa = *(const float4*)(tbl + i0 * D + d0);
                    const float4 fb = *(const float4*)(tbl + (i0 + 1) * D + d0);
                    fx = fa.x + fr * (fb.x - fa.x);
                    fy = fa.y + fr * (fb.y - fa.y);
                    fz = fa.z + fr * (fb.z - fa.z);
                    fw = fa.w + fr * (fb.w - fa.w);
                } else {
                    const float dist = -t;   // exact fallback (dist > DMAXF), ~never taken
                    fx = b2[d0]; fy = b2[d0 + 1]; fz = b2[d0 + 2]; fw = b2[d0 + 3];
                    for (int q = 0; q < Hh; ++q) {
                        float hv = silu_f(dist * W1[q] + b1[q]);
                        fx += hv * W2[q * D + d0];
                        fy += hv * W2[q * D + d0 + 1];
                        fz += hv * W2[q * D + d0 + 2];
                        fw += hv * W2[q * D + d0 + 3];
                    }
                }
                ax += hb[j].x * fx; ay += hb[j].y * fy;
                az += hb[j].z * fz; aw += hb[j].w * fw;
            }
        }
        // tail
        for (; e0 < end; ++e0) {
            const int2 e2 = g_edge[e0];
            const int c = e2.x;
            const float t = __int_as_float(e2.y);
            const float4 h4 = *(const float4*)(h + c * D + d0);
            float fx, fy, fz, fw;
            if (t >= 0.f) {
                int i0 = (int)t; i0 = min(i0, T_TBL - 2);
                const float fr = t - (float)i0;
                const float4 fa = *(const float4*)(tbl + i0 * D + d0);
                const float4 fb = *(const float4*)(tbl + (i0 + 1) * D + d0);
                fx = fa.x + fr * (fb.x - fa.x);
                fy = fa.y + fr * (fb.y - fa.y);
                fz = fa.z + fr * (fb.z - fa.z);
                fw = fa.w + fr * (fb.w - fa.w);
            } else {
                const float dist = -t;
                fx = b2[d0]; fy = b2[d0 + 1]; fz = b2[d0 + 2]; fw = b2[d0 + 3];
                for (int q = 0; q < Hh; ++q) {
                    float hv = silu_f(dist * W1[q] + b1[q]);
                    fx += hv * W2[q * D + d0];
                    fy += hv * W2[q * D + d0 + 1];
                    fz += hv * W2[q * D + d0 + 2];
                    fw += hv * W2[q * D + d0 + 3];
                }
            }
            ax += h4.x * fx; ay += h4.y * fy; az += h4.z * fz; aw += h4.w * fw;
        }

        const float inv = 1.f / fmaxf((float)(end - beg), 1.f);
        float4 o; o.x = ax * inv; o.y = ay * inv; o.z = az * inv; o.w = aw * inv;
        *(float4*)(g_agg + v * D + d0) = o;
    }
}

// ---------------- K6: fused node MLP: [h|agg]@W3 + b3 -> LN -> SiLU -> @W4 + b4 ----
// block = 32 nodes, 256 threads. thread(tx,ty): nodes ty*4+j, GEMM1 cols tx*8..+7 (4 f32x2 pairs)
#define SM_IN_STRIDE 260
__global__ __launch_bounds__(256, 2)
void k_mlp(const float* __restrict__ h,
           const float* __restrict__ W3, const float* __restrict__ b3,
           const float* __restrict__ gam, const float* __restrict__ bet,
           const float* __restrict__ W4, const float* __restrict__ b4,
           float* __restrict__ out, int nn) {
    extern __shared__ float sm[];
    float* in_s = sm;                    // [32][260]
    float* wt = sm + 32 * SM_IN_STRIDE;  // [2][4096] W3 tiles (reused [2][2048] for W4)

    const int tid = threadIdx.x;
    const int tx = tid & 31, ty = tid >> 5;
    const int node0 = blockIdx.x * 32;

    // load input tile [h | agg] -> in_s[node][k]
    {
        const int n = tid >> 3, seg = tid & 7;
        const int gn = min(node0 + n, nn - 1);
        const float* src = (seg < 4) ? (h + gn * D + seg * 32)
                                     : (g_agg + gn * D + (seg - 4) * 32);
        float* dst = in_s + n * SM_IN_STRIDE + seg * 32;
#pragma unroll
        for (int i = 0; i < 8; ++i) ((float4*)dst)[i] = ((const float4*)src)[i];
    }

    // preload W3 tile 0
    float4 pre[4];
#pragma unroll
    for (int i = 0; i < 4; ++i) pre[i] = ((const float4*)W3)[tid + i * 256];
#pragma unroll
    for (int i = 0; i < 4; ++i) ((float4*)wt)[tid + i * 256] = pre[i];
    __syncthreads();

    ull acc[4][4];
#pragma unroll
    for (int j = 0; j < 4; ++j)
#pragma unroll
        for (int p = 0; p < 4; ++p) acc[j][p] = 0ull;

    const float* r0 = in_s + (ty * 4 + 0) * SM_IN_STRIDE;
    const float* r1 = in_s + (ty * 4 + 1) * SM_IN_STRIDE;
    const float* r2 = in_s + (ty * 4 + 2) * SM_IN_STRIDE;
    const float* r3 = in_s + (ty * 4 + 3) * SM_IN_STRIDE;

#pragma unroll 1
    for (int t = 0; t < 16; ++t) {
        float* cur = wt + (t & 1) * 4096;
        float* nxt = wt + ((t + 1) & 1) * 4096;
        if (t < 15) {
            const float4* gs = (const float4*)(W3 + (t + 1) * 4096);
#pragma unroll
            for (int i = 0; i < 4; ++i) pre[i] = gs[tid + i * 256];
        }
#pragma unroll
        for (int kk = 0; kk < 16; ++kk) {
            const int k = t * 16 + kk;
            const ull a0 = pack2(r0[k], r0[k]);
            const ull a1 = pack2(r1[k], r1[k]);
            const ull a2 = pack2(r2[k], r2[k]);
            const ull a3 = pack2(r3[k], r3[k]);
            const ull* br = (const ull*)(cur + kk * 256 + tx * 8);
            const ull b0 = br[0], b1v = br[1], b2v = br[2], b3v = br[3];
            ffma2(acc[0][0], a0, b0); ffma2(acc[0][1], a0, b1v); ffma2(acc[0][2], a0, b2v); ffma2(acc[0][3], a0, b3v);
            ffma2(acc[1][0], a1, b0); ffma2(acc[1][1], a1, b1v); ffma2(acc[1][2], a1, b2v); ffma2(acc[1][3], a1, b3v);
            ffma2(acc[2][0], a2, b0); ffma2(acc[2][1], a2, b1v); ffma2(acc[2][2], a2, b2v); ffma2(acc[2][3], a2, b3v);
            ffma2(acc[3][0], a3, b0); ffma2(acc[3][1], a3, b1v); ffma2(acc[3][2], a3, b2v); ffma2(acc[3][3], a3, b3v);
        }
        if (t < 15) {
#pragma unroll
            for (int i = 0; i < 4; ++i) ((float4*)nxt)[tid + i * 256] = pre[i];
            __syncthreads();
        }
    }

    // bias + LayerNorm + SiLU, write back into in_s (rows are warp-private)
    float2 u[4][4];
    {
        const float4 bbl = *(const float4*)(b3 + tx * 8);
        const float4 bbh = *(const float4*)(b3 + tx * 8 + 4);
        const float bv[8] = {bbl.x, bbl.y, bbl.z, bbl.w, bbh.x, bbh.y, bbh.z, bbh.w};
#pragma unroll
        for (int j = 0; j < 4; ++j)
#pragma unroll
            for (int p = 0; p < 4; ++p) {
                unpack2(acc[j][p], u[j][p].x, u[j][p].y);
                u[j][p].x += bv[2 * p]; u[j][p].y += bv[2 * p + 1];
            }
    }
    {
        const float4 g0 = *(const float4*)(gam + tx * 8);
        const float4 g1 = *(const float4*)(gam + tx * 8 + 4);
        const float4 e0 = *(const float4*)(bet + tx * 8);
        const float4 e1 = *(const float4*)(bet + tx * 8 + 4);
        const float gv[8] = {g0.x, g0.y, g0.z, g0.w, g1.x, g1.y, g1.z, g1.w};
        const float ev[8] = {e0.x, e0.y, e0.z, e0.w, e1.x, e1.y, e1.z, e1.w};
#pragma unroll
        for (int j = 0; j < 4; ++j) {
            float s = 0.f, q = 0.f;
#pragma unroll
            for (int p = 0; p < 4; ++p) {
                s += u[j][p].x + u[j][p].y;
                q += u[j][p].x * u[j][p].x + u[j][p].y * u[j][p].y;
            }
#pragma unroll
            for (int dsh = 16; dsh; dsh >>= 1) {
                s += __shfl_xor_sync(0xffffffffu, s, dsh);
                q += __shfl_xor_sync(0xffffffffu, q, dsh);
            }
            const float mu = s * (1.f / 256.f);
            const float var = q * (1.f / 256.f) - mu * mu;
            const float rs = rsqrtf(var + 1e-5f);
            float* urow = in_s + (ty * 4 + j) * SM_IN_STRIDE + tx * 8;
#pragma unroll
            for (int p = 0; p < 4; ++p) {
                const float ux = (u[j][p].x - mu) * rs * gv[2 * p] + ev[2 * p];
                const float uy = (u[j][p].y - mu) * rs * gv[2 * p + 1] + ev[2 * p + 1];
                urow[2 * p] = silu_f(ux);
                urow[2 * p + 1] = silu_f(uy);
            }
        }
    }
    __syncwarp();

    // GEMM2: out = U @ W4 + b4. thread: 4 nodes x 4 cols (2 f32x2 pairs)
    float4 pre2[2];
#pragma unroll
    for (int i = 0; i < 2; ++i) pre2[i] = ((const float4*)W4)[tid + i * 256];
#pragma unroll
    for (int i = 0; i < 2; ++i) ((float4*)wt)[tid + i * 256] = pre2[i];
    __syncthreads();   // also fences stragglers off W3 tile15 / their in_s rows

    ull acc2[4][2];
#pragma unroll
    for (int j = 0; j < 4; ++j) { acc2[j][0] = 0ull; acc2[j][1] = 0ull; }

#pragma unroll 1
    for (int t = 0; t < 16; ++t) {
        float* cur = wt + (t & 1) * 2048;
        float* nxt = wt + ((t + 1) & 1) * 2048;
        if (t < 15) {
            const float4* gs = (const float4*)(W4 + (t + 1) * 2048);
            pre2[0] = gs[tid]; pre2[1] = gs[tid + 256];
        }
#pragma unroll
        for (int kk = 0; kk < 16; ++kk) {
            const int k = t * 16 + kk;
            const ull a0 = pack2(r0[k], r0[k]);
            const ull a1 = pack2(r1[k], r1[k]);
            const ull a2 = pack2(r2[k], r2[k]);
            const ull a3 = pack2(r3[k], r3[k]);
            const ull* br = (const ull*)(cur + kk * 128 + tx * 4);
            const ull b0 = br[0], b1v = br[1];
            ffma2(acc2[0][0], a0, b0); ffma2(acc2[0][1], a0, b1v);
            ffma2(acc2[1][0], a1, b0); ffma2(acc2[1][1], a1, b1v);
            ffma2(acc2[2][0], a2, b0); ffma2(acc2[2][1], a2, b1v);
            ffma2(acc2[3][0], a3, b0); ffma2(acc2[3][1], a3, b1v);
        }
        if (t < 15) {
            ((float4*)nxt)[tid] = pre2[0];
            ((float4*)nxt)[tid + 256] = pre2[1];
            __syncthreads();
        }
    }

    // epilogue
    const float4 b4v = *(const float4*)(b4 + tx * 4);
#pragma unroll
    for (int j = 0; j < 4; ++j) {
        float2 o0, o1;
        unpack2(acc2[j][0], o0.x, o0.y);
        unpack2(acc2[j][1], o1.x, o1.y);
        o0.x += b4v.x; o0.y += b4v.y; o1.x += b4v.z; o1.y += b4v.w;
        const int gn = node0 + ty * 4 + j;
        if (gn < nn) {
            float2* op = (float2*)(out + gn * D + tx * 4);
            op[0] = o0; op[1] = o1;
        }
    }
}

// ---------------- host ----------------
extern "C" void kernel_launch(void* const* d_in, const int* in_sizes, int n_in,
                              void* d_out, int out_size) {
    const float* x = (const float*)d_in[0];
    const float* h = (const float*)d_in[1];
    const int* ei = (const int*)d_in[2];    // edge_indices: int32
    int base = 3;
    if (n_in >= 14 && in_sizes[3] == 1) base = 4;   // batch_size scalar present
    const float* W1 = (const float*)d_in[base + 0];
    const float* b1 = (const float*)d_in[base + 1];
    const float* W2 = (const float*)d_in[base + 2];
    const float* b2 = (const float*)d_in[base + 3];
    const float* W3 = (const float*)d_in[base + 4];
    const float* b3 = (const float*)d_in[base + 5];
    const float* gam = (const float*)d_in[base + 6];
    const float* bet = (const float*)d_in[base + 7];
    const float* W4 = (const float*)d_in[base + 8];
    const float* b4 = (const float*)d_in[base + 9];
    float* out = (float*)d_out;

    int E = in_sizes[2] / 2;
    int nn = in_sizes[1] / D;
    if (E > MAXE) E = MAXE;
    if (nn > MAXN) nn = MAXN;

    const int agg_smem = T_TBL * D * 4;                          // 196608
    const int mlp_smem = (32 * SM_IN_STRIDE + 2 * 4096) * 4;     // 66048
    cudaFuncSetAttribute(k_agg, cudaFuncAttributeMaxDynamicSharedMemorySize, agg_smem);
    cudaFuncSetAttribute(k_mlp, cudaFuncAttributeMaxDynamicSharedMemorySize, mlp_smem);

    const int e4 = (E + 3) / 4;
    k_table<<<T_TBL, 128>>>(W1, b1, W2, b2);
    k_count<<<(e4 + 255) / 256, 256>>>(ei, E, nn);
    k_scan<<<1, 1024>>>(E);
    k_scatter<<<(E + 255) / 256, 256>>>(ei, x, E, nn);
    k_agg<<<148, 512, agg_smem>>>(h, W1, b1, W2, b2, nn);
    k_mlp<<<(nn + 31) / 32, 256, mlp_smem>>>(h, W3, b3, gam, bet, W4, b4, out, nn);
}

// round 13
// speedup vs baseline: 1.2621x; 1.0216x over previous
#include <cuda_runtime.h>

#define D 128
#define Hh 256
#define T_TBL 384
#define DMAXF 12.0f
#define MAXE 524288
#define MAXN 16384

typedef unsigned long long ull;

// ---------------- scratch (no allocs allowed; 16B-aligned) ----------------
__device__ __align__(16) float g_filt[T_TBL * D];      // filter table (fp32)
__device__ __align__(16) int   g_cnt[MAXN];
__device__ __align__(16) int   g_off[MAXN + 4];
__device__ __align__(16) int   g_rank[MAXE];           // within-row rank of each edge
__device__ __align__(16) int2  g_edge[MAXE];           // {col, float_bits(tcoord)} bucketed
__device__ __align__(16) float g_agg[MAXN * D];

// ---------------- helpers ----------------
__device__ __forceinline__ ull pack2(float x, float y) {
    ull r; asm("mov.b64 %0, {%1,%2};" : "=l"(r) : "f"(x), "f"(y)); return r;
}
__device__ __forceinline__ void unpack2(ull v, float& x, float& y) {
    asm("mov.b64 {%0,%1}, %2;" : "=f"(x), "=f"(y) : "l"(v));
}
__device__ __forceinline__ void ffma2(ull& c, ull a, ull b) {
    asm("fma.rn.f32x2 %0, %1, %2, %0;" : "+l"(c) : "l"(a), "l"(b));
}
__device__ __forceinline__ float silu_f(float z) {
    return z / (1.f + __expf(-z));
}

// ---------------- K1: build filter table (+ zero g_cnt; 384*128 threads >= MAXN) ----
__global__ void k_table(const float* __restrict__ W1, const float* __restrict__ b1,
                        const float* __restrict__ W2, const float* __restrict__ b2) {
    __shared__ float hid[Hh];
    const int t = blockIdx.x, tid = threadIdx.x;   // 128 threads
    const int gid = t * 128 + tid;
    if (gid < MAXN) g_cnt[gid] = 0;
    const float dist = t * (DMAXF / (float)(T_TBL - 1));
    for (int j = tid; j < Hh; j += 128) hid[j] = silu_f(dist * W1[j] + b1[j]);
    __syncthreads();
    float s = b2[tid];
#pragma unroll 8
    for (int j = 0; j < Hh; ++j) s += hid[j] * W2[j * D + tid];
    g_filt[t * D + tid] = s;
}

// ---------------- K2: count edges per row; record rank (8 edges/thread ILP) --------
__global__ void k_count(const int* __restrict__ ei, int E, int nn) {
    int e = (blockIdx.x * blockDim.x + threadIdx.x) * 8;
    if (e + 7 < E) {
        int4 v0 = *(const int4*)(ei + e);
        int4 v1 = *(const int4*)(ei + e + 4);
        unsigned r[8] = {(unsigned)v0.x, (unsigned)v0.y, (unsigned)v0.z, (unsigned)v0.w,
                         (unsigned)v1.x, (unsigned)v1.y, (unsigned)v1.z, (unsigned)v1.w};
        int k[8];
#pragma unroll
        for (int j = 0; j < 8; ++j) {
            if (r[j] >= (unsigned)nn) r[j] = 0;
            k[j] = atomicAdd(&g_cnt[r[j]], 1);
        }
        int4 o0 = make_int4(k[0], k[1], k[2], k[3]);
        int4 o1 = make_int4(k[4], k[5], k[6], k[7]);
        *(int4*)(g_rank + e) = o0;
        *(int4*)(g_rank + e + 4) = o1;
    } else {
        for (; e < E; ++e) {
            unsigned r = (unsigned)ei[e];
            if (r >= (unsigned)nn) r = 0;
            g_rank[e] = atomicAdd(&g_cnt[r], 1);
        }
    }
}

// ---------------- K3: exclusive scan of fixed MAXN counts (int4 vectorized) ----------
__global__ void k_scan(int Etot) {
    __shared__ int wsum[32];
    const int tid = threadIdx.x;
    const int lane = tid & 31, wid = tid >> 5;
    const int b0 = tid * 16;
    int4 cv[4];
    const int4* cp = (const int4*)(g_cnt + b0);
#pragma unroll
    for (int q = 0; q < 4; ++q) cv[q] = cp[q];
    int vals[16];
    int s = 0;
#pragma unroll
    for (int q = 0; q < 4; ++q) {
        vals[q * 4 + 0] = s; s += cv[q].x;
        vals[q * 4 + 1] = s; s += cv[q].y;
        vals[q * 4 + 2] = s; s += cv[q].z;
        vals[q * 4 + 3] = s; s += cv[q].w;
    }
    int inc = s;
#pragma unroll
    for (int d = 1; d < 32; d <<= 1) {
        int o = __shfl_up_sync(0xffffffffu, inc, d);
        if (lane >= d) inc += o;
    }
    if (lane == 31) wsum[wid] = inc;
    __syncthreads();
    if (wid == 0) {
        int v = wsum[lane];
#pragma unroll
        for (int d = 1; d < 32; d <<= 1) {
            int o = __shfl_up_sync(0xffffffffu, v, d);
            if (lane >= d) v += o;
        }
        wsum[lane] = v;
    }
    __syncthreads();
    const int base = (inc - s) + (wid ? wsum[wid - 1] : 0);
    int4* op = (int4*)(g_off + b0);
#pragma unroll
    for (int q = 0; q < 4; ++q) {
        int4 o;
        o.x = base + vals[q * 4 + 0];
        o.y = base + vals[q * 4 + 1];
        o.z = base + vals[q * 4 + 2];
        o.w = base + vals[q * 4 + 3];
        op[q] = o;
    }
    if (tid == 1023) g_off[MAXN] = Etot;
}

// ---------------- K4: atomic-free bucket scatter (2 edges/thread ILP) --------------
__global__ void k_scatter(const int* __restrict__ ei, const float* __restrict__ x,
                          int E, int nn) {
    const int e0 = (blockIdx.x * blockDim.x + threadIdx.x) * 2;
    if (e0 >= E) return;
    const bool two = (e0 + 1 < E);
    const int e1 = two ? e0 + 1 : e0;

    unsigned r0 = (unsigned)__ldg(ei + e0), r1 = (unsigned)__ldg(ei + e1);
    unsigned c0 = (unsigned)__ldg(ei + E + e0), c1 = (unsigned)__ldg(ei + E + e1);
    if (r0 >= (unsigned)nn) r0 = 0;
    if (r1 >= (unsigned)nn) r1 = 0;
    if (c0 >= (unsigned)nn) c0 = 0;
    if (c1 >= (unsigned)nn) c1 = 0;

    const int off0 = g_off[r0], off1 = g_off[r1];
    const int rk0 = g_rank[e0], rk1 = g_rank[e1];

    const float ax0 = __ldg(x + r0 * 3 + 0), ay0 = __ldg(x + r0 * 3 + 1), az0 = __ldg(x + r0 * 3 + 2);
    const float bx0 = __ldg(x + c0 * 3 + 0), by0 = __ldg(x + c0 * 3 + 1), bz0 = __ldg(x + c0 * 3 + 2);
    const float ax1 = __ldg(x + r1 * 3 + 0), ay1 = __ldg(x + r1 * 3 + 1), az1 = __ldg(x + r1 * 3 + 2);
    const float bx1 = __ldg(x + c1 * 3 + 0), by1 = __ldg(x + c1 * 3 + 1), bz1 = __ldg(x + c1 * 3 + 2);

    const float dx0 = ax0 - bx0, dy0 = ay0 - by0, dz0 = az0 - bz0;
    const float dx1 = ax1 - bx1, dy1 = ay1 - by1, dz1 = az1 - bz1;
    const float dist0 = sqrtf(dx0 * dx0 + dy0 * dy0 + dz0 * dz0);
    const float dist1 = sqrtf(dx1 * dx1 + dy1 * dy1 + dz1 * dz1);
    const float t0 = (dist0 <= DMAXF) ? dist0 * ((float)(T_TBL - 1) / DMAXF) : -dist0;
    const float t1 = (dist1 <= DMAXF) ? dist1 * ((float)(T_TBL - 1) / DMAXF) : -dist1;

    int2 o0; o0.x = (int)c0; o0.y = __float_as_int(t0);
    g_edge[off0 + rk0] = o0;
    if (two) {
        int2 o1; o1.x = (int)c1; o1.y = __float_as_int(t1);
        g_edge[off1 + rk1] = o1;
    }
}

// ---------------- K5: aggregate (warp/node; table in SMEM; MLP=8; 768 thr) ---------
__global__ __launch_bounds__(768, 1)
void k_agg(const float* __restrict__ h,
           const float* __restrict__ W1, const float* __restrict__ b1,
           const float* __restrict__ W2, const float* __restrict__ b2, int nn) {
    extern __shared__ float tbl[];   // [T_TBL][D]
    for (int i = threadIdx.x; i < T_TBL * D / 4; i += blockDim.x)
        ((float4*)tbl)[i] = ((const float4*)g_filt)[i];
    __syncthreads();

    const int lane = threadIdx.x & 31;
    const int gw = (blockIdx.x * blockDim.x + threadIdx.x) >> 5;
    const int nwarps = (gridDim.x * blockDim.x) >> 5;
    const int d0 = lane * 4;

    for (int v = gw; v < nn; v += nwarps) {
        const int beg = g_off[v], end = g_off[v + 1];
        float ax = 0.f, ay = 0.f, az = 0.f, aw = 0.f;

        // prefetched edge descriptor for the upcoming 8-edge round (lanes 0..7)
        int2 ed = make_int2(0, 0);
        if (lane < 8 && beg + lane < end) ed = g_edge[beg + lane];

        int e0 = beg;
        for (; e0 + 8 <= end; e0 += 8) {
            const int2 cur = ed;
            if (lane < 8 && e0 + 8 + lane < end) ed = g_edge[e0 + 8 + lane];

            float4 hb[8];
            float  tc[8];
#pragma unroll
            for (int j = 0; j < 8; ++j) {
                const int c = __shfl_sync(0xffffffffu, cur.x, j);
                tc[j] = __int_as_float(__shfl_sync(0xffffffffu, cur.y, j));
                hb[j] = *(const float4*)(h + c * D + d0);
            }
#pragma unroll
            for (int j = 0; j < 8; ++j) {
                const float t = tc[j];
                float fx, fy, fz, fw;
                if (t >= 0.f) {
                    int i0 = (int)t; i0 = min(i0, T_TBL - 2);
                    const float fr = t - (float)i0;
                    const float4 fa = *(const float4*)(tbl + i0 * D + d0);
                    const float4 fb = *(const float4*)(tbl + (i0 + 1) * D + d0);
                    fx = fa.x + fr * (fb.x - fa.x);
                    fy = fa.y + fr * (fb.y - fa.y);
                    fz = fa.z + fr * (fb.z - fa.z);
                    fw = fa.w + fr * (fb.w - fa.w);
                } else {
                    const float dist = -t;   // exact fallback (dist > DMAXF), ~never taken
                    fx = b2[d0]; fy = b2[d0 + 1]; fz = b2[d0 + 2]; fw = b2[d0 + 3];
                    for (int q = 0; q < Hh; ++q) {
                        float hv = silu_f(dist * W1[q] + b1[q]);
                        fx += hv * W2[q * D + d0];
                        fy += hv * W2[q * D + d0 + 1];
                        fz += hv * W2[q * D + d0 + 2];
                        fw += hv * W2[q * D + d0 + 3];
                    }
                }
                ax += hb[j].x * fx; ay += hb[j].y * fy;
                az += hb[j].z * fz; aw += hb[j].w * fw;
            }
        }
        // tail
        for (; e0 < end; ++e0) {
            const int2 e2 = g_edge[e0];
            const int c = e2.x;
            const float t = __int_as_float(e2.y);
            const float4 h4 = *(const float4*)(h + c * D + d0);
            float fx, fy, fz, fw;
            if (t >= 0.f) {
                int i0 = (int)t; i0 = min(i0, T_TBL - 2);
                const float fr = t - (float)i0;
                const float4 fa = *(const float4*)(tbl + i0 * D + d0);
                const float4 fb = *(const float4*)(tbl + (i0 + 1) * D + d0);
                fx = fa.x + fr * (fb.x - fa.x);
                fy = fa.y + fr * (fb.y - fa.y);
                fz = fa.z + fr * (fb.z - fa.z);
                fw = fa.w + fr * (fb.w - fa.w);
            } else {
                const float dist = -t;
                fx = b2[d0]; fy = b2[d0 + 1]; fz = b2[d0 + 2]; fw = b2[d0 + 3];
                for (int q = 0; q < Hh; ++q) {
                    float hv = silu_f(dist * W1[q] + b1[q]);
                    fx += hv * W2[q * D + d0];
                    fy += hv * W2[q * D + d0 + 1];
                    fz += hv * W2[q * D + d0 + 2];
                    fw += hv * W2[q * D + d0 + 3];
                }
            }
            ax += h4.x * fx; ay += h4.y * fy; az += h4.z * fz; aw += h4.w * fw;
        }

        const float inv = 1.f / fmaxf((float)(end - beg), 1.f);
        float4 o; o.x = ax * inv; o.y = ay * inv; o.z = az * inv; o.w = aw * inv;
        *(float4*)(g_agg + v * D + d0) = o;
    }
}

// ---------------- K6: fused node MLP: [h|agg]@W3 + b3 -> LN -> SiLU -> @W4 + b4 ----
// block = 32 nodes, 256 threads. thread(tx,ty): nodes ty*4+j, GEMM1 cols tx*8..+7 (4 f32x2 pairs)
#define SM_IN_STRIDE 260
__global__ __launch_bounds__(256, 2)
void k_mlp(const float* __restrict__ h,
           const float* __restrict__ W3, const float* __restrict__ b3,
           const float* __restrict__ gam, const float* __restrict__ bet,
           const float* __restrict__ W4, const float* __restrict__ b4,
           float* __restrict__ out, int nn) {
    extern __shared__ float sm[];
    float* in_s = sm;                    // [32][260]
    float* wt = sm + 32 * SM_IN_STRIDE;  // [2][4096] W3 tiles (reused [2][2048] for W4)

    const int tid = threadIdx.x;
    const int tx = tid & 31, ty = tid >> 5;
    const int node0 = blockIdx.x * 32;

    // load input tile [h | agg] -> in_s[node][k]
    {
        const int n = tid >> 3, seg = tid & 7;
        const int gn = min(node0 + n, nn - 1);
        const float* src = (seg < 4) ? (h + gn * D + seg * 32)
                                     : (g_agg + gn * D + (seg - 4) * 32);
        float* dst = in_s + n * SM_IN_STRIDE + seg * 32;
#pragma unroll
        for (int i = 0; i < 8; ++i) ((float4*)dst)[i] = ((const float4*)src)[i];
    }

    // preload W3 tile 0
    float4 pre[4];
#pragma unroll
    for (int i = 0; i < 4; ++i) pre[i] = ((const float4*)W3)[tid + i * 256];
#pragma unroll
    for (int i = 0; i < 4; ++i) ((float4*)wt)[tid + i * 256] = pre[i];
    __syncthreads();

    ull acc[4][4];
#pragma unroll
    for (int j = 0; j < 4; ++j)
#pragma unroll
        for (int p = 0; p < 4; ++p) acc[j][p] = 0ull;

    const float* r0 = in_s + (ty * 4 + 0) * SM_IN_STRIDE;
    const float* r1 = in_s + (ty * 4 + 1) * SM_IN_STRIDE;
    const float* r2 = in_s + (ty * 4 + 2) * SM_IN_STRIDE;
    const float* r3 = in_s + (ty * 4 + 3) * SM_IN_STRIDE;

#pragma unroll 1
    for (int t = 0; t < 16; ++t) {
        float* cur = wt + (t & 1) * 4096;
        float* nxt = wt + ((t + 1) & 1) * 4096;
        if (t < 15) {
            const float4* gs = (const float4*)(W3 + (t + 1) * 4096);
#pragma unroll
            for (int i = 0; i < 4; ++i) pre[i] = gs[tid + i * 256];
        }
#pragma unroll
        for (int kk = 0; kk < 16; ++kk) {
            const int k = t * 16 + kk;
            const ull a0 = pack2(r0[k], r0[k]);
            const ull a1 = pack2(r1[k], r1[k]);
            const ull a2 = pack2(r2[k], r2[k]);
            const ull a3 = pack2(r3[k], r3[k]);
            const ull* br = (const ull*)(cur + kk * 256 + tx * 8);
            const ull b0 = br[0], b1v = br[1], b2v = br[2], b3v = br[3];
            ffma2(acc[0][0], a0, b0); ffma2(acc[0][1], a0, b1v); ffma2(acc[0][2], a0, b2v); ffma2(acc[0][3], a0, b3v);
            ffma2(acc[1][0], a1, b0); ffma2(acc[1][1], a1, b1v); ffma2(acc[1][2], a1, b2v); ffma2(acc[1][3], a1, b3v);
            ffma2(acc[2][0], a2, b0); ffma2(acc[2][1], a2, b1v); ffma2(acc[2][2], a2, b2v); ffma2(acc[2][3], a2, b3v);
            ffma2(acc[3][0], a3, b0); ffma2(acc[3][1], a3, b1v); ffma2(acc[3][2], a3, b2v); ffma2(acc[3][3], a3, b3v);
        }
        if (t < 15) {
#pragma unroll
            for (int i = 0; i < 4; ++i) ((float4*)nxt)[tid + i * 256] = pre[i];
            __syncthreads();
        }
    }

    // bias + LayerNorm + SiLU, write back into in_s (rows are warp-private)
    float2 u[4][4];
    {
        const float4 bbl = *(const float4*)(b3 + tx * 8);
        const float4 bbh = *(const float4*)(b3 + tx * 8 + 4);
        const float bv[8] = {bbl.x, bbl.y, bbl.z, bbl.w, bbh.x, bbh.y, bbh.z, bbh.w};
#pragma unroll
        for (int j = 0; j < 4; ++j)
#pragma unroll
            for (int p = 0; p < 4; ++p) {
                unpack2(acc[j][p], u[j][p].x, u[j][p].y);
                u[j][p].x += bv[2 * p]; u[j][p].y += bv[2 * p + 1];
            }
    }
    {
        const float4 g0 = *(const float4*)(gam + tx * 8);
        const float4 g1 = *(const float4*)(gam + tx * 8 + 4);
        const float4 e0 = *(const float4*)(bet + tx * 8);
        const float4 e1 = *(const float4*)(bet + tx * 8 + 4);
        const float gv[8] = {g0.x, g0.y, g0.z, g0.w, g1.x, g1.y, g1.z, g1.w};
        const float ev[8] = {e0.x, e0.y, e0.z, e0.w, e1.x, e1.y, e1.z, e1.w};
#pragma unroll
        for (int j = 0; j < 4; ++j) {
            float s = 0.f, q = 0.f;
#pragma unroll
            for (int p = 0; p < 4; ++p) {
                s += u[j][p].x + u[j][p].y;
                q += u[j][p].x * u[j][p].x + u[j][p].y * u[j][p].y;
            }
#pragma unroll
            for (int dsh = 16; dsh; dsh >>= 1) {
                s += __shfl_xor_sync(0xffffffffu, s, dsh);
                q += __shfl_xor_sync(0xffffffffu, q, dsh);
            }
            const float mu = s * (1.f / 256.f);
            const float var = q * (1.f / 256.f) - mu * mu;
            const float rs = rsqrtf(var + 1e-5f);
            float* urow = in_s + (ty * 4 + j) * SM_IN_STRIDE + tx * 8;
#pragma unroll
            for (int p = 0; p < 4; ++p) {
                const float ux = (u[j][p].x - mu) * rs * gv[2 * p] + ev[2 * p];
                const float uy = (u[j][p].y - mu) * rs * gv[2 * p + 1] + ev[2 * p + 1];
                urow[2 * p] = silu_f(ux);
                urow[2 * p + 1] = silu_f(uy);
            }
        }
    }
    __syncwarp();

    // GEMM2: out = U @ W4 + b4. thread: 4 nodes x 4 cols (2 f32x2 pairs)
    float4 pre2[2];
#pragma unroll
    for (int i = 0; i < 2; ++i) pre2[i] = ((const float4*)W4)[tid + i * 256];
#pragma unroll
    for (int i = 0; i < 2; ++i) ((float4*)wt)[tid + i * 256] = pre2[i];
    __syncthreads();   // also fences stragglers off W3 tile15 / their in_s rows

    ull acc2[4][2];
#pragma unroll
    for (int j = 0; j < 4; ++j) { acc2[j][0] = 0ull; acc2[j][1] = 0ull; }

#pragma unroll 1
    for (int t = 0; t < 16; ++t) {
        float* cur = wt + (t & 1) * 2048;
        float* nxt = wt + ((t + 1) & 1) * 2048;
        if (t < 15) {
            const float4* gs = (const float4*)(W4 + (t + 1) * 2048);
            pre2[0] = gs[tid]; pre2[1] = gs[tid + 256];
        }
#pragma unroll
        for (int kk = 0; kk < 16; ++kk) {
            const int k = t * 16 + kk;
            const ull a0 = pack2(r0[k], r0[k]);
            const ull a1 = pack2(r1[k], r1[k]);
            const ull a2 = pack2(r2[k], r2[k]);
            const ull a3 = pack2(r3[k], r3[k]);
            const ull* br = (const ull*)(cur + kk * 128 + tx * 4);
            const ull b0 = br[0], b1v = br[1];
            ffma2(acc2[0][0], a0, b0); ffma2(acc2[0][1], a0, b1v);
            ffma2(acc2[1][0], a1, b0); ffma2(acc2[1][1], a1, b1v);
            ffma2(acc2[2][0], a2, b0); ffma2(acc2[2][1], a2, b1v);
            ffma2(acc2[3][0], a3, b0); ffma2(acc2[3][1], a3, b1v);
        }
        if (t < 15) {
            ((float4*)nxt)[tid] = pre2[0];
            ((float4*)nxt)[tid + 256] = pre2[1];
            __syncthreads();
        }
    }

    // epilogue
    const float4 b4v = *(const float4*)(b4 + tx * 4);
#pragma unroll
    for (int j = 0; j < 4; ++j) {
        float2 o0, o1;
        unpack2(acc2[j][0], o0.x, o0.y);
        unpack2(acc2[j][1], o1.x, o1.y);
        o0.x += b4v.x; o0.y += b4v.y; o1.x += b4v.z; o1.y += b4v.w;
        const int gn = node0 + ty * 4 + j;
        if (gn < nn) {
            float2* op = (float2*)(out + gn * D + tx * 4);
            op[0] = o0; op[1] = o1;
        }
    }
}

// ---------------- host ----------------
extern "C" void kernel_launch(void* const* d_in, const int* in_sizes, int n_in,
                              void* d_out, int out_size) {
    const float* x = (const float*)d_in[0];
    const float* h = (const float*)d_in[1];
    const int* ei = (const int*)d_in[2];    // edge_indices: int32
    int base = 3;
    if (n_in >= 14 && in_sizes[3] == 1) base = 4;   // batch_size scalar present
    const float* W1 = (const float*)d_in[base + 0];
    const float* b1 = (const float*)d_in[base + 1];
    const float* W2 = (const float*)d_in[base + 2];
    const float* b2 = (const float*)d_in[base + 3];
    const float* W3 = (const float*)d_in[base + 4];
    const float* b3 = (const float*)d_in[base + 5];
    const float* gam = (const float*)d_in[base + 6];
    const float* bet = (const float*)d_in[base + 7];
    const float* W4 = (const float*)d_in[base + 8];
    const float* b4 = (const float*)d_in[base + 9];
    float* out = (float*)d_out;

    int E = in_sizes[2] / 2;
    int nn = in_sizes[1] / D;
    if (E > MAXE) E = MAXE;
    if (nn > MAXN) nn = MAXN;

    const int agg_smem = T_TBL * D * 4;                          // 196608
    const int mlp_smem = (32 * SM_IN_STRIDE + 2 * 4096) * 4;     // 66048
    cudaFuncSetAttribute(k_agg, cudaFuncAttributeMaxDynamicSharedMemorySize, agg_smem);
    cudaFuncSetAttribute(k_mlp, cudaFuncAttributeMaxDynamicSharedMemorySize, mlp_smem);

    const int e8 = (E + 7) / 8;
    const int e2 = (E + 1) / 2;
    k_table<<<T_TBL, 128>>>(W1, b1, W2, b2);
    k_count<<<(e8 + 255) / 256, 256>>>(ei, E, nn);
    k_scan<<<1, 1024>>>(E);
    k_scatter<<<(e2 + 255) / 256, 256>>>(ei, x, E, nn);
    k_agg<<<148, 768, agg_smem>>>(h, W1, b1, W2, b2, nn);
    k_mlp<<<(nn + 31) / 32, 256, mlp_smem>>>(h, W3, b3, gam, bet, W4, b4, out, nn);
}